// round 4
// baseline (speedup 1.0000x reference)
#include <cuda_runtime.h>

#define B_    4
#define T_    4096
#define D_    1024
#define H_    16
#define DH_   64
#define NS_   4
#define CTX_  516
#define Q0_   3580
#define MTOT_ (B_*CTX_)   // 2064

// Scratch (static device globals; no allocation allowed)
__device__ float g_Q[MTOT_*D_];
__device__ float g_K[MTOT_*D_];
__device__ float g_V[MTOT_*D_];
__device__ float g_AO[MTOT_*D_];

// ---------------------------------------------------------------------------
// Zero-fill the structurally-zero output rows (t < Q0 for each batch)
// ---------------------------------------------------------------------------
__global__ void zero_kernel(float* __restrict__ out) {
    size_t idx = (size_t)blockIdx.x * blockDim.x + threadIdx.x;
    const size_t n4 = (size_t)B_ * Q0_ * D_ / 4;
    if (idx < n4) {
        size_t e = idx * 4;
        const size_t perb = (size_t)Q0_ * D_;
        size_t b = e / perb;
        size_t r = e % perb;
        *(float4*)(out + b * (size_t)T_ * D_ + r) = make_float4(0.f, 0.f, 0.f, 0.f);
    }
}

// ---------------------------------------------------------------------------
// High-AI fp32 GEMM: 128x128 block tile, BK=8, 256 threads, 8x8 per thread,
// double-buffered smem. A rows gathered (sink/window token mapping).
// ---------------------------------------------------------------------------
#define BM 128
#define BN 128
#define BK 8

struct GemmSmem {
    float As[2][BK][BM];
    float Bs[2][BK][BN];
};

// The whole mainloop, shared between qkv and oproj via inlining.
// aptr: this thread's global A pointer (row base + seg offset), or null (pads).
// bptr: this thread's global B pointer for k-row 'brow', col n0+bcol.
__device__ __forceinline__ void gemm_mainloop(
    GemmSmem& sm, const float* aptr, const float* bptr,
    int arow, int aseg, int brow, int bcol,
    int ty, int tx, float acc[8][8])
{
    // Prefetch tile 0
    float4 av = make_float4(0.f, 0.f, 0.f, 0.f);
    if (aptr) av = *(const float4*)(aptr);
    float4 bv = *(const float4*)(bptr);
    sm.As[0][aseg + 0][arow] = av.x;
    sm.As[0][aseg + 1][arow] = av.y;
    sm.As[0][aseg + 2][arow] = av.z;
    sm.As[0][aseg + 3][arow] = av.w;
    *(float4*)&sm.Bs[0][brow][bcol] = bv;
    __syncthreads();

    int buf = 0;
    for (int kt = BK; kt <= D_; kt += BK) {
        const bool has_next = (kt < D_);
        float4 an = make_float4(0.f, 0.f, 0.f, 0.f), bn;
        if (has_next) {
            if (aptr) an = *(const float4*)(aptr + kt);
            bn = *(const float4*)(bptr + (size_t)kt * D_);
        }

        #pragma unroll
        for (int k = 0; k < BK; k++) {
            float4 a0 = *(const float4*)&sm.As[buf][k][ty * 4];
            float4 a1 = *(const float4*)&sm.As[buf][k][64 + ty * 4];
            float4 b0 = *(const float4*)&sm.Bs[buf][k][tx * 4];
            float4 b1 = *(const float4*)&sm.Bs[buf][k][64 + tx * 4];
            float ar[8] = {a0.x, a0.y, a0.z, a0.w, a1.x, a1.y, a1.z, a1.w};
            float br[8] = {b0.x, b0.y, b0.z, b0.w, b1.x, b1.y, b1.z, b1.w};
            #pragma unroll
            for (int r = 0; r < 8; r++)
                #pragma unroll
                for (int c = 0; c < 8; c++)
                    acc[r][c] += ar[r] * br[c];
        }

        if (has_next) {
            int nb = buf ^ 1;
            sm.As[nb][aseg + 0][arow] = an.x;
            sm.As[nb][aseg + 1][arow] = an.y;
            sm.As[nb][aseg + 2][arow] = an.z;
            sm.As[nb][aseg + 3][arow] = an.w;
            *(float4*)&sm.Bs[nb][brow][bcol] = bn;
            __syncthreads();
            buf = nb;
        }
    }
}

__global__ __launch_bounds__(256) void qkv_gemm(
    const float* __restrict__ x,
    const float* __restrict__ Wq,
    const float* __restrict__ Wk,
    const float* __restrict__ Wv)
{
    __shared__ GemmSmem sm;
    const int z = blockIdx.z;
    const float* __restrict__ W = (z == 0) ? Wq : ((z == 1) ? Wk : Wv);
    float* __restrict__ outp = (z == 0) ? g_Q : ((z == 1) ? g_K : g_V);

    const int tid = threadIdx.x;
    const int tx = tid & 15, ty = tid >> 4;
    const int m0 = blockIdx.y * BM, n0 = blockIdx.x * BN;

    // A-load mapping: 128 rows x 2 float4 segments
    const int arow = tid >> 1;
    const int aseg = (tid & 1) * 4;
    const int m = m0 + arow;
    const float* aptr = nullptr;
    if (m < MTOT_) {
        int b = m / CTX_, i = m % CTX_;
        int tok = (z == 0) ? (Q0_ + i) : (i < NS_ ? i : (Q0_ + i));
        aptr = x + (size_t)(b * T_ + tok) * D_ + aseg;
    }
    // B-load mapping: 8 k-rows x 32 float4 columns
    const int brow = tid >> 5;
    const int bcol = (tid & 31) * 4;
    const float* bptr = W + (size_t)brow * D_ + n0 + bcol;

    float acc[8][8] = {};
    gemm_mainloop(sm, aptr, bptr, arow, aseg, brow, bcol, ty, tx, acc);

    #pragma unroll
    for (int r = 0; r < 8; r++) {
        int mm = m0 + ((r < 4) ? (ty * 4 + r) : (64 + ty * 4 + r - 4));
        if (mm < MTOT_) {
            float* op = outp + (size_t)mm * D_ + n0;
            *(float4*)(op + tx * 4)      = make_float4(acc[r][0], acc[r][1], acc[r][2], acc[r][3]);
            *(float4*)(op + 64 + tx * 4) = make_float4(acc[r][4], acc[r][5], acc[r][6], acc[r][7]);
        }
    }
}

__global__ __launch_bounds__(256) void oproj_gemm(
    const float* __restrict__ Wo,
    float* __restrict__ out)
{
    __shared__ GemmSmem sm;
    const int tid = threadIdx.x;
    const int tx = tid & 15, ty = tid >> 4;
    const int m0 = blockIdx.y * BM, n0 = blockIdx.x * BN;

    const int arow = tid >> 1;
    const int aseg = (tid & 1) * 4;
    const int m = m0 + arow;
    const float* aptr = (m < MTOT_) ? (g_AO + (size_t)m * D_ + aseg) : nullptr;

    const int brow = tid >> 5;
    const int bcol = (tid & 31) * 4;
    const float* bptr = Wo + (size_t)brow * D_ + n0 + bcol;

    float acc[8][8] = {};
    gemm_mainloop(sm, aptr, bptr, arow, aseg, brow, bcol, ty, tx, acc);

    #pragma unroll
    for (int r = 0; r < 8; r++) {
        int mm = m0 + ((r < 4) ? (ty * 4 + r) : (64 + ty * 4 + r - 4));
        if (mm < MTOT_) {
            int b = mm / CTX_, i = mm % CTX_;
            float* op = out + (size_t)(b * T_ + Q0_ + i) * D_ + n0;
            *(float4*)(op + tx * 4)      = make_float4(acc[r][0], acc[r][1], acc[r][2], acc[r][3]);
            *(float4*)(op + 64 + tx * 4) = make_float4(acc[r][4], acc[r][5], acc[r][6], acc[r][7]);
        }
    }
}

// ---------------------------------------------------------------------------
// Attention: one thread per query, causal over 516-ctx, online softmax.
// ---------------------------------------------------------------------------
#define BQ 128
#define KT 64

__global__ __launch_bounds__(BQ) void attn_kernel() {
    const int b = blockIdx.z, h = blockIdx.y, qt = blockIdx.x;
    const int qi = qt * BQ + threadIdx.x;
    const bool act = qi < CTX_;

    float qreg[DH_];
    #pragma unroll
    for (int d = 0; d < DH_; d++) qreg[d] = 0.f;
    if (act) {
        const float* qp = g_Q + (size_t)(b * CTX_ + qi) * D_ + h * DH_;
        #pragma unroll
        for (int d = 0; d < DH_; d += 4) {
            float4 v = *(const float4*)(qp + d);
            qreg[d] = v.x; qreg[d + 1] = v.y; qreg[d + 2] = v.z; qreg[d + 3] = v.w;
        }
    }

    float acc[DH_];
    #pragma unroll
    for (int d = 0; d < DH_; d++) acc[d] = 0.f;
    float mval = -1e30f, lsum = 0.f;

    __shared__ float Ks[KT][DH_];
    __shared__ float Vs[KT][DH_];

    const int jmax = min(CTX_ - 1, qt * BQ + BQ - 1);
    for (int j0 = 0; j0 <= jmax; j0 += KT) {
        for (int it = threadIdx.x; it < KT * DH_ / 4; it += BQ) {
            int jj = it >> 4;
            int dd = (it & 15) * 4;
            int j = j0 + jj;
            float4 kv = make_float4(0.f, 0.f, 0.f, 0.f);
            float4 vv = make_float4(0.f, 0.f, 0.f, 0.f);
            if (j < CTX_) {
                size_t off = (size_t)(b * CTX_ + j) * D_ + h * DH_ + dd;
                kv = *(const float4*)(g_K + off);
                vv = *(const float4*)(g_V + off);
            }
            *(float4*)&Ks[jj][dd] = kv;
            *(float4*)&Vs[jj][dd] = vv;
        }
        __syncthreads();

        int jend = act ? min(KT, qi - j0 + 1) : 0;
        for (int jj = 0; jj < jend; jj++) {
            float s0 = 0.f, s1 = 0.f, s2 = 0.f, s3 = 0.f;
            #pragma unroll
            for (int d = 0; d < DH_; d += 4) {
                s0 += qreg[d + 0] * Ks[jj][d + 0];
                s1 += qreg[d + 1] * Ks[jj][d + 1];
                s2 += qreg[d + 2] * Ks[jj][d + 2];
                s3 += qreg[d + 3] * Ks[jj][d + 3];
            }
            float s = ((s0 + s1) + (s2 + s3)) * 0.125f;
            float mn = fmaxf(mval, s);
            float c = __expf(mval - mn);
            float p = __expf(s - mn);
            lsum = lsum * c + p;
            #pragma unroll
            for (int d = 0; d < DH_; d++)
                acc[d] = acc[d] * c + p * Vs[jj][d];
            mval = mn;
        }
        __syncthreads();
    }

    if (act) {
        float inv = 1.f / lsum;
        float* op = g_AO + (size_t)(b * CTX_ + qi) * D_ + h * DH_;
        #pragma unroll
        for (int d = 0; d < DH_; d += 4) {
            float4 v = make_float4(acc[d] * inv, acc[d + 1] * inv,
                                   acc[d + 2] * inv, acc[d + 3] * inv);
            *(float4*)(op + d) = v;
        }
    }
}

// ---------------------------------------------------------------------------
extern "C" void kernel_launch(void* const* d_in, const int* in_sizes, int n_in,
                              void* d_out, int out_size) {
    const float* x  = (const float*)d_in[0];
    const float* Wq = (const float*)d_in[1];
    const float* Wk = (const float*)d_in[2];
    const float* Wv = (const float*)d_in[3];
    const float* Wo = (const float*)d_in[4];
    float* out = (float*)d_out;

    // 1. Zero the structurally-zero rows (output poisoned to 0xAA)
    {
        size_t n4 = (size_t)B_ * Q0_ * D_ / 4;
        int th = 256;
        int bl = (int)((n4 + th - 1) / th);
        zero_kernel<<<bl, th>>>(out);
    }

    // 2. Q/K/V projections for only the 2064 live rows
    {
        dim3 g(D_ / BN, (MTOT_ + BM - 1) / BM, 3);
        qkv_gemm<<<g, 256>>>(x, Wq, Wk, Wv);
    }

    // 3. Causal attention over the 516-entry context
    {
        dim3 g((CTX_ + BQ - 1) / BQ, H_, B_);
        attn_kernel<<<g, BQ>>>();
    }

    // 4. Output projection, scattered to live rows
    {
        dim3 g(D_ / BN, (MTOT_ + BM - 1) / BM, 1);
        oproj_gemm<<<g, 256>>>(Wo, out);
    }
}

// round 6
// speedup vs baseline: 1.6979x; 1.6979x over previous
#include <cuda_runtime.h>
#include <cuda_bf16.h>
#include <cstdint>

#define B_    4
#define T_    4096
#define D_    1024
#define H_    16
#define DH_   64
#define NS_   4
#define CTX_  516
#define Q0_   3580
#define MTOT_ (B_*CTX_)   // 2064
#define XR_   520         // per-batch gathered x rows: 4 sinks + 516 window

// ---------------------------------------------------------------------------
// Device scratch (no allocation allowed)
// ---------------------------------------------------------------------------
__device__ __align__(16) __nv_bfloat16 g_Xh[B_*XR_*D_];
__device__ __align__(16) __nv_bfloat16 g_Xl[B_*XR_*D_];
__device__ __align__(16) __nv_bfloat16 g_Wth[4*D_*D_];   // W^T hi: [z][n][k]
__device__ __align__(16) __nv_bfloat16 g_Wtl[4*D_*D_];   // W^T lo
__device__ __align__(16) float g_Q[MTOT_*D_];
__device__ __align__(16) float g_K[MTOT_*D_];
__device__ __align__(16) float g_V[MTOT_*D_];
__device__ __align__(16) __nv_bfloat16 g_AOh[MTOT_*D_];
__device__ __align__(16) __nv_bfloat16 g_AOl[MTOT_*D_];

// ---------------------------------------------------------------------------
__device__ __forceinline__ uint32_t smem_u32(const void* p) {
    uint32_t a;
    asm("{ .reg .u64 t; cvta.to.shared.u64 t, %1; cvt.u32.u64 %0, t; }" : "=r"(a) : "l"(p));
    return a;
}
__device__ __forceinline__ uint32_t pack_bf2(float a, float b) {
    return ((uint32_t)__bfloat16_as_ushort(__float2bfloat16_rn(b)) << 16) |
           (uint32_t)__bfloat16_as_ushort(__float2bfloat16_rn(a));
}
__device__ __forceinline__ void ldsm4(uint32_t* r, uint32_t addr) {
    asm volatile("ldmatrix.sync.aligned.m8n8.x4.shared.b16 {%0,%1,%2,%3}, [%4];"
        : "=r"(r[0]), "=r"(r[1]), "=r"(r[2]), "=r"(r[3]) : "r"(addr));
}
__device__ __forceinline__ void ldsm2(uint32_t* r, uint32_t addr) {
    asm volatile("ldmatrix.sync.aligned.m8n8.x2.shared.b16 {%0,%1}, [%2];"
        : "=r"(r[0]), "=r"(r[1]) : "r"(addr));
}
__device__ __forceinline__ void mma16816(float* c, const uint32_t* a, const uint32_t* b) {
    asm volatile(
        "mma.sync.aligned.m16n8k16.row.col.f32.bf16.bf16.f32 "
        "{%0,%1,%2,%3}, {%4,%5,%6,%7}, {%8,%9}, {%0,%1,%2,%3};"
        : "+f"(c[0]), "+f"(c[1]), "+f"(c[2]), "+f"(c[3])
        : "r"(a[0]), "r"(a[1]), "r"(a[2]), "r"(a[3]), "r"(b[0]), "r"(b[1]));
}

// ---------------------------------------------------------------------------
// Zero-fill the structurally-zero output rows
// ---------------------------------------------------------------------------
__global__ void zero_kernel(float* __restrict__ out) {
    size_t idx = (size_t)blockIdx.x * blockDim.x + threadIdx.x;
    const size_t n4 = (size_t)B_ * Q0_ * D_ / 4;
    if (idx < n4) {
        size_t e = idx * 4;
        const size_t perb = (size_t)Q0_ * D_;
        size_t b = e / perb, r = e % perb;
        *(float4*)(out + b * (size_t)T_ * D_ + r) = make_float4(0.f, 0.f, 0.f, 0.f);
    }
}

// ---------------------------------------------------------------------------
// prep_x: gather live x rows, split fp32 -> bf16 hi/lo
// ---------------------------------------------------------------------------
__global__ __launch_bounds__(256) void prep_x(const float* __restrict__ x) {
    int gr = blockIdx.x;            // 0..2079
    int b = gr / XR_, r = gr % XR_;
    int tok = (r < NS_) ? r : (Q0_ + (r - NS_));
    int t = threadIdx.x;
    float4 v = *(const float4*)(x + (size_t)(b * T_ + tok) * D_ + t * 4);
    float h0 = __bfloat162float(__float2bfloat16_rn(v.x));
    float h1 = __bfloat162float(__float2bfloat16_rn(v.y));
    float h2 = __bfloat162float(__float2bfloat16_rn(v.z));
    float h3 = __bfloat162float(__float2bfloat16_rn(v.w));
    uint2 hw = make_uint2(pack_bf2(v.x, v.y), pack_bf2(v.z, v.w));
    uint2 lw = make_uint2(pack_bf2(v.x - h0, v.y - h1), pack_bf2(v.z - h2, v.w - h3));
    ((uint2*)g_Xh)[(size_t)gr * 256 + t] = hw;
    ((uint2*)g_Xl)[(size_t)gr * 256 + t] = lw;
}

// ---------------------------------------------------------------------------
// prep_w: transpose W (4 matrices) -> [n][k] bf16 hi/lo
// grid (D/32 n-tiles, D/64 k-tiles, 4), block (32, 8)
// ---------------------------------------------------------------------------
__global__ __launch_bounds__(256) void prep_w(
    const float* __restrict__ Wq, const float* __restrict__ Wk,
    const float* __restrict__ Wv, const float* __restrict__ Wo)
{
    const int z = blockIdx.z;
    const float* __restrict__ W = (z == 0) ? Wq : (z == 1) ? Wk : (z == 2) ? Wv : Wo;
    __shared__ float tile[64][33];
    const int n0 = blockIdx.x * 32, k0 = blockIdx.y * 64;
    const int tx = threadIdx.x, ty = threadIdx.y;

    #pragma unroll
    for (int rr = 0; rr < 8; rr++) {
        int kk = ty + rr * 8;                // 0..63
        tile[kk][tx] = W[(size_t)(k0 + kk) * D_ + n0 + tx];
    }
    __syncthreads();
    #pragma unroll
    for (int rr = 0; rr < 4; rr++) {         // n = 0..31 only (tile is 32 wide)
        int n = ty + rr * 8;
        float v0 = tile[tx * 2][n], v1 = tile[tx * 2 + 1][n];
        float h0 = __bfloat162float(__float2bfloat16_rn(v0));
        float h1 = __bfloat162float(__float2bfloat16_rn(v1));
        size_t base = (size_t)z * D_ * D_ + (size_t)(n0 + n) * D_ + k0;
        ((uint32_t*)(g_Wth + base))[tx] = pack_bf2(v0, v1);
        ((uint32_t*)(g_Wtl + base))[tx] = pack_bf2(v0 - h0, v1 - h1);
    }
}

// ---------------------------------------------------------------------------
// Tensor-core GEMM via mma.sync: C[128x128] = A(hi/lo) x B(hi/lo)^T, K=1024.
// mode 0/1/2: A = gathered x (g_Xh/l), out = g_Q/g_K/g_V
// mode 3    : A = g_AOh/l,            out = final (scattered rows)
// 8 warps in 2x4 grid; warp tile 64x32; K-chunk 32; 3-term hi/lo split.
// ---------------------------------------------------------------------------
#define GM 128
#define GN 128
#define KC 32
#define SPAD 40
#define NCHUNK (D_/KC)   // 32

__global__ __launch_bounds__(256) void gemm_mma(int mode_base, float* __restrict__ outF) {
    __shared__ __nv_bfloat16 sAh[GM * SPAD];
    __shared__ __nv_bfloat16 sAl[GM * SPAD];
    __shared__ __nv_bfloat16 sBh[GN * SPAD];
    __shared__ __nv_bfloat16 sBl[GN * SPAD];

    const int mode = mode_base + blockIdx.z;
    const int n0 = blockIdx.x * GN;
    const int m0 = blockIdx.y * GM;
    const int tid = threadIdx.x;
    const int wid = tid >> 5, lane = tid & 31;
    const int warp_m = (wid & 1) * 64;       // 2 warps along m
    const int warp_n = (wid >> 1) * 32;      // 4 warps along n

    const __nv_bfloat16* __restrict__ Bh_g = g_Wth + (size_t)mode * D_ * D_;
    const __nv_bfloat16* __restrict__ Bl_g = g_Wtl + (size_t)mode * D_ * D_;
    const __nv_bfloat16* __restrict__ Ah_g = (mode < 3) ? g_Xh : g_AOh;
    const __nv_bfloat16* __restrict__ Al_g = (mode < 3) ? g_Xl : g_AOl;

    // Loader geometry: 256 threads cover 128 rows x 4 quads (8 halves each); two
    // row-groups (r, r+64) per thread per tile.
    const int ar0 = tid >> 2, ar1 = ar0 + 64;
    const int q = tid & 3;
    long asrc0 = -1, asrc1 = -1;
    {
        int m = m0 + ar0;
        if (m < MTOT_) {
            if (mode < 3) { int b = m / CTX_, i = m % CTX_; asrc0 = (long)b * XR_ + ((mode == 0) ? (NS_ + i) : ((i < NS_) ? i : (NS_ + i))); }
            else asrc0 = m;
        }
        m = m0 + ar1;
        if (m < MTOT_) {
            if (mode < 3) { int b = m / CTX_, i = m % CTX_; asrc1 = (long)b * XR_ + ((mode == 0) ? (NS_ + i) : ((i < NS_) ? i : (NS_ + i))); }
            else asrc1 = m;
        }
    }
    const int soff0 = ar0 * SPAD + q * 8;
    const int soff1 = ar1 * SPAD + q * 8;

    float acc[4][4][4];
    #pragma unroll
    for (int a = 0; a < 4; a++)
        #pragma unroll
        for (int b = 0; b < 4; b++)
            #pragma unroll
            for (int cc = 0; cc < 4; cc++) acc[a][b][cc] = 0.f;

    uint4 pf[8];
    const uint4 zv = make_uint4(0, 0, 0, 0);
    auto fetch = [&](int c) {
        const size_t koff = (size_t)c * KC + q * 8;
        pf[0] = (asrc0 >= 0) ? *(const uint4*)(Ah_g + (size_t)asrc0 * D_ + koff) : zv;
        pf[1] = (asrc1 >= 0) ? *(const uint4*)(Ah_g + (size_t)asrc1 * D_ + koff) : zv;
        pf[2] = (asrc0 >= 0) ? *(const uint4*)(Al_g + (size_t)asrc0 * D_ + koff) : zv;
        pf[3] = (asrc1 >= 0) ? *(const uint4*)(Al_g + (size_t)asrc1 * D_ + koff) : zv;
        pf[4] = *(const uint4*)(Bh_g + (size_t)(n0 + ar0) * D_ + koff);
        pf[5] = *(const uint4*)(Bh_g + (size_t)(n0 + ar1) * D_ + koff);
        pf[6] = *(const uint4*)(Bl_g + (size_t)(n0 + ar0) * D_ + koff);
        pf[7] = *(const uint4*)(Bl_g + (size_t)(n0 + ar1) * D_ + koff);
    };

    // fragment smem addresses (constant across chunks)
    const int a_row = (lane & 15), a_kh = (lane >> 4) << 3;
    const int b_row = (lane & 7),  b_kh = ((lane >> 3) & 1) << 3;
    uint32_t aAh[4], aAl[4], aBh[4], aBl[4];
    #pragma unroll
    for (int mt = 0; mt < 4; mt++) {
        int r = warp_m + mt * 16 + a_row;
        aAh[mt] = smem_u32(sAh + r * SPAD + a_kh);
        aAl[mt] = smem_u32(sAl + r * SPAD + a_kh);
    }
    #pragma unroll
    for (int nt = 0; nt < 4; nt++) {
        int r = warp_n + nt * 8 + b_row;
        aBh[nt] = smem_u32(sBh + r * SPAD + b_kh);
        aBl[nt] = smem_u32(sBl + r * SPAD + b_kh);
    }

    fetch(0);
    for (int c = 0; c < NCHUNK; c++) {
        *(uint4*)(sAh + soff0) = pf[0];
        *(uint4*)(sAh + soff1) = pf[1];
        *(uint4*)(sAl + soff0) = pf[2];
        *(uint4*)(sAl + soff1) = pf[3];
        *(uint4*)(sBh + soff0) = pf[4];
        *(uint4*)(sBh + soff1) = pf[5];
        *(uint4*)(sBl + soff0) = pf[6];
        *(uint4*)(sBl + soff1) = pf[7];
        __syncthreads();
        if (c + 1 < NCHUNK) fetch(c + 1);

        #pragma unroll
        for (int ks = 0; ks < KC * 2; ks += 32) {   // ks in bytes (16 halves)
            uint32_t fAh[4][4], fAl[4][4], fBh[4][2], fBl[4][2];
            #pragma unroll
            for (int mt = 0; mt < 4; mt++) {
                ldsm4(fAh[mt], aAh[mt] + ks);
                ldsm4(fAl[mt], aAl[mt] + ks);
            }
            #pragma unroll
            for (int nt = 0; nt < 4; nt++) {
                ldsm2(fBh[nt], aBh[nt] + ks);
                ldsm2(fBl[nt], aBl[nt] + ks);
            }
            #pragma unroll
            for (int mt = 0; mt < 4; mt++)
                #pragma unroll
                for (int nt = 0; nt < 4; nt++) {
                    mma16816(acc[mt][nt], fAh[mt], fBh[nt]);
                    mma16816(acc[mt][nt], fAh[mt], fBl[nt]);
                    mma16816(acc[mt][nt], fAl[mt], fBh[nt]);
                }
        }
        __syncthreads();
    }

    // Epilogue: c0,c1 -> row lane/4; c2,c3 -> row lane/4+8; cols (lane%4)*2
    const int er = lane >> 2, ec = (lane & 3) * 2;
    #pragma unroll
    for (int mt = 0; mt < 4; mt++) {
        #pragma unroll
        for (int half = 0; half < 2; half++) {
            int mm = m0 + warp_m + mt * 16 + er + half * 8;
            if (mm < MTOT_) {
                float* dst;
                if (mode < 3) {
                    float* outp = (mode == 0) ? g_Q : (mode == 1) ? g_K : g_V;
                    dst = outp + (size_t)mm * D_ + n0;
                } else {
                    int b = mm / CTX_, i = mm % CTX_;
                    dst = outF + (size_t)(b * T_ + Q0_ + i) * D_ + n0;
                }
                #pragma unroll
                for (int nt = 0; nt < 4; nt++) {
                    float2 v = make_float2(acc[mt][nt][half * 2], acc[mt][nt][half * 2 + 1]);
                    *(float2*)(dst + warp_n + nt * 8 + ec) = v;
                }
            }
        }
    }
}

// ---------------------------------------------------------------------------
// Attention: one thread per query, lazy-rescale online softmax.
// Emits AO as bf16 hi/lo for the tensor-core output projection.
// ---------------------------------------------------------------------------
#define BQ 128
#define KT 64

__global__ __launch_bounds__(BQ) void attn_kernel() {
    const int b = blockIdx.z, h = blockIdx.y, qt = blockIdx.x;
    const int qi = qt * BQ + threadIdx.x;
    const bool act = qi < CTX_;

    float qreg[DH_];
    #pragma unroll
    for (int d = 0; d < DH_; d++) qreg[d] = 0.f;
    if (act) {
        const float* qp = g_Q + (size_t)(b * CTX_ + qi) * D_ + h * DH_;
        #pragma unroll
        for (int d = 0; d < DH_; d += 4) {
            float4 v = *(const float4*)(qp + d);
            qreg[d] = v.x; qreg[d + 1] = v.y; qreg[d + 2] = v.z; qreg[d + 3] = v.w;
        }
    }

    float acc[DH_];
    #pragma unroll
    for (int d = 0; d < DH_; d++) acc[d] = 0.f;
    float mval = -1e30f, lsum = 0.f;

    __shared__ float Ks[KT][DH_];
    __shared__ float Vs[KT][DH_];

    const int jmax = min(CTX_ - 1, qt * BQ + BQ - 1);
    for (int j0 = 0; j0 <= jmax; j0 += KT) {
        for (int it = threadIdx.x; it < KT * DH_ / 4; it += BQ) {
            int jj = it >> 4;
            int dd = (it & 15) * 4;
            int j = j0 + jj;
            float4 kv = make_float4(0.f, 0.f, 0.f, 0.f);
            float4 vv = make_float4(0.f, 0.f, 0.f, 0.f);
            if (j < CTX_) {
                size_t off = (size_t)(b * CTX_ + j) * D_ + h * DH_ + dd;
                kv = *(const float4*)(g_K + off);
                vv = *(const float4*)(g_V + off);
            }
            *(float4*)&Ks[jj][dd] = kv;
            *(float4*)&Vs[jj][dd] = vv;
        }
        __syncthreads();

        int jend = act ? min(KT, qi - j0 + 1) : 0;
        for (int jj = 0; jj < jend; jj++) {
            float s0 = 0.f, s1 = 0.f, s2 = 0.f, s3 = 0.f;
            #pragma unroll
            for (int d = 0; d < DH_; d += 4) {
                s0 += qreg[d + 0] * Ks[jj][d + 0];
                s1 += qreg[d + 1] * Ks[jj][d + 1];
                s2 += qreg[d + 2] * Ks[jj][d + 2];
                s3 += qreg[d + 3] * Ks[jj][d + 3];
            }
            float s = ((s0 + s1) + (s2 + s3)) * 0.125f;
            if (s <= mval) {
                float p = __expf(s - mval);
                lsum += p;
                #pragma unroll
                for (int d = 0; d < DH_; d++) acc[d] += p * Vs[jj][d];
            } else {
                float cc = __expf(mval - s);
                mval = s;
                lsum = lsum * cc + 1.f;
                #pragma unroll
                for (int d = 0; d < DH_; d++) acc[d] = acc[d] * cc + Vs[jj][d];
            }
        }
        __syncthreads();
    }

    if (act) {
        float inv = 1.f / lsum;
        size_t base = (size_t)(b * CTX_ + qi) * D_ + h * DH_;
        #pragma unroll
        for (int d = 0; d < DH_; d += 2) {
            float o0 = acc[d] * inv, o1 = acc[d + 1] * inv;
            float h0 = __bfloat162float(__float2bfloat16_rn(o0));
            float h1 = __bfloat162float(__float2bfloat16_rn(o1));
            *(uint32_t*)(g_AOh + base + d) = pack_bf2(o0, o1);
            *(uint32_t*)(g_AOl + base + d) = pack_bf2(o0 - h0, o1 - h1);
        }
    }
}

// ---------------------------------------------------------------------------
extern "C" void kernel_launch(void* const* d_in, const int* in_sizes, int n_in,
                              void* d_out, int out_size) {
    const float* x  = (const float*)d_in[0];
    const float* Wq = (const float*)d_in[1];
    const float* Wk = (const float*)d_in[2];
    const float* Wv = (const float*)d_in[3];
    const float* Wo = (const float*)d_in[4];
    float* out = (float*)d_out;

    // 1. Zero structurally-zero output rows
    {
        size_t n4 = (size_t)B_ * Q0_ * D_ / 4;
        zero_kernel<<<(int)((n4 + 255) / 256), 256>>>(out);
    }
    // 2. Prep: gather+split x rows; transpose+split weights
    prep_x<<<B_ * XR_, 256>>>(x);
    prep_w<<<dim3(D_ / 32, D_ / 64, 4), dim3(32, 8)>>>(Wq, Wk, Wv, Wo);

    // 3. Q/K/V projections on tensor cores (modes 0,1,2)
    gemm_mma<<<dim3(D_ / GN, (MTOT_ + GM - 1) / GM, 3), 256>>>(0, nullptr);

    // 4. Attention
    attn_kernel<<<dim3((CTX_ + BQ - 1) / BQ, H_, B_), BQ>>>();

    // 5. Output projection (mode 3), scattered to live rows
    gemm_mma<<<dim3(D_ / GN, (MTOT_ + GM - 1) / GM, 1), 256>>>(3, out);
}